// round 2
// baseline (speedup 1.0000x reference)
#include <cuda_runtime.h>
#include <cstdint>
#include <math.h>

// Problem dims
#define Hd 2048
#define Ed 16
#define Td 2048
#define Id 1408
#define ISd 2816

// ---------------- scratch (static device globals; no allocs) ----------------
__device__ float g_act[4096 * 1408];     // compact routed activations (silu(g)*u)
__device__ float g_sact[2048 * 2816];    // shared-expert activations
__device__ int   g_slot_token[4096];
__device__ float g_slot_w[4096];
__device__ int   g_topk_idx[2048 * 2];
__device__ float g_topk_w[2048 * 2];
__device__ int   g_counts[16];
__device__ int   g_cursor[16];
__device__ int   g_offs[16];

// ---------------- helpers ----------------
__device__ __forceinline__ uint32_t f2tf32(float f) {
    uint32_t r;
    asm("cvt.rna.tf32.f32 %0, %1;\n" : "=r"(r) : "f"(f));
    return r;
}

__device__ __forceinline__ void mma8(float* c, const uint32_t* a, uint32_t b0, uint32_t b1) {
    asm volatile(
        "mma.sync.aligned.m16n8k8.row.col.f32.tf32.tf32.f32 "
        "{%0,%1,%2,%3}, {%4,%5,%6,%7}, {%8,%9}, {%0,%1,%2,%3};\n"
        : "+f"(c[0]), "+f"(c[1]), "+f"(c[2]), "+f"(c[3])
        : "r"(a[0]), "r"(a[1]), "r"(a[2]), "r"(a[3]), "r"(b0), "r"(b1));
}

__device__ __forceinline__ void cp16(float* s, const float* g, bool pred) {
    uint32_t sa = (uint32_t)__cvta_generic_to_shared(s);
    int sz = pred ? 16 : 0;
    asm volatile("cp.async.cg.shared.global [%0], [%1], 16, %2;\n"
                 :: "r"(sa), "l"(g), "r"(sz));
}

// ---------------- tiny kernels ----------------
__global__ void zero_kernel() {
    if (threadIdx.x < 16) { g_counts[threadIdx.x] = 0; g_cursor[threadIdx.x] = 0; }
}

__global__ void scan_kernel() {
    if (threadIdx.x == 0) {
        int off = 0;
        #pragma unroll
        for (int e = 0; e < 16; e++) { g_offs[e] = off; off += g_counts[e]; }
    }
}

__global__ void dispatch_kernel() {
    int t = blockIdx.x * blockDim.x + threadIdx.x;
    if (t < Td) {
        #pragma unroll
        for (int k = 0; k < 2; k++) {
            int e = g_topk_idx[2 * t + k];
            int p = atomicAdd(&g_cursor[e], 1);
            int s = g_offs[e] + p;
            g_slot_token[s] = t;
            g_slot_w[s] = g_topk_w[2 * t + k];
        }
    }
}

// One warp per token: logits -> softmax -> top-2 -> histogram
__global__ void __launch_bounds__(128) router_kernel(const float* __restrict__ x,
                                                     const float* __restrict__ gw) {
    int lane = threadIdx.x & 31;
    int t = blockIdx.x * 4 + (threadIdx.x >> 5);
    if (t >= Td) return;
    float xr[64];
    const float* xp = x + (size_t)t * Hd;
    #pragma unroll
    for (int j = 0; j < 64; j++) xr[j] = xp[lane + 32 * j];
    float logit[16];
    #pragma unroll
    for (int e = 0; e < 16; e++) {
        const float* g = gw + e * Hd;
        float s = 0.f;
        #pragma unroll
        for (int j = 0; j < 64; j++) s = fmaf(xr[j], g[lane + 32 * j], s);
        #pragma unroll
        for (int o = 16; o > 0; o >>= 1) s += __shfl_xor_sync(0xffffffffu, s, o);
        logit[e] = s;
    }
    if (lane == 0) {
        float mx = logit[0];
        #pragma unroll
        for (int e = 1; e < 16; e++) mx = fmaxf(mx, logit[e]);
        float p[16]; float den = 0.f;
        #pragma unroll
        for (int e = 0; e < 16; e++) { p[e] = expf(logit[e] - mx); den += p[e]; }
        int i1 = 0; float v1 = p[0];
        #pragma unroll
        for (int e = 1; e < 16; e++) if (p[e] > v1) { v1 = p[e]; i1 = e; }
        int i2 = -1; float v2 = -1.f;
        #pragma unroll
        for (int e = 0; e < 16; e++) if (e != i1 && p[e] > v2) { v2 = p[e]; i2 = e; }
        float inv = 1.f / den;
        g_topk_idx[2 * t]     = i1;
        g_topk_idx[2 * t + 1] = i2;
        g_topk_w[2 * t]       = v1 * inv;
        g_topk_w[2 * t + 1]   = v2 * inv;
        atomicAdd(&g_counts[i1], 1);
        atomicAdd(&g_counts[i2], 1);
    }
}

// ---------------- fused gate+up GEMM (tf32 mma), writes silu(g)*u ----------------
// Tile: 128(M) x 64(N per matrix) x 32(K). 256 threads, warps 4x2.
// Stage layout (floats): A[128][36] @0 (4608), Bg[32][72] @4608, Bu[32][72] @6912.
// STAGE = 9216 floats.
template <bool GATHER>
__global__ void __launch_bounds__(256) gateup_kernel(const float* __restrict__ X,
                                                     const float* __restrict__ Wg,
                                                     const float* __restrict__ Wu,
                                                     int N) {
    extern __shared__ float sm[];
    __shared__ int tok_s[128];
    const int tid = threadIdx.x;
    const int lane = tid & 31, wid = tid >> 5;
    const int wm = wid & 3, wn = wid >> 2;
    const int e = blockIdx.z;
    const int n0 = blockIdx.x * 64;
    const int r0 = blockIdx.y * 128;

    int C, base;
    if (GATHER) { C = g_counts[e]; base = g_offs[e]; }
    else        { C = Td;          base = 0; }
    if (r0 >= C) return;

    const float* WgE = Wg + (size_t)e * Hd * N;
    const float* WuE = Wu + (size_t)e * Hd * N;
    float* ACT = GATHER ? g_act : g_sact;

    if (tid < 128) {
        int r = r0 + tid;
        tok_s[tid] = GATHER ? ((r < C) ? g_slot_token[base + r] : -1) : r;
    }
    __syncthreads();

    auto issue = [&](int st, int kt) {
        float* As = sm + st * 9216;
        float* Bg = As + 4608;
        float* Bu = As + 6912;
        int k0 = kt * 32;
        #pragma unroll
        for (int i = 0; i < 4; i++) {
            int idx = tid + i * 256;
            int row = idx >> 3, kc = (idx & 7) * 4;
            int tok = tok_s[row];
            const float* src = X + (size_t)(tok < 0 ? 0 : tok) * Hd + k0 + kc;
            cp16(&As[row * 36 + kc], src, tok >= 0);
        }
        #pragma unroll
        for (int i = 0; i < 2; i++) {
            int idx = tid + i * 256;
            int row = idx >> 4, nc = (idx & 15) * 4;
            size_t go = (size_t)(k0 + row) * N + n0 + nc;
            cp16(&Bg[row * 72 + nc], WgE + go, true);
            cp16(&Bu[row * 72 + nc], WuE + go, true);
        }
        asm volatile("cp.async.commit_group;\n");
    };

    float accg[2][4][4] = {};
    float accu[2][4][4] = {};

    auto compute = [&](int st) {
        const float* As = sm + st * 9216;
        const float* Bg = As + 4608;
        const float* Bu = As + 6912;
        #pragma unroll
        for (int kk = 0; kk < 4; kk++) {
            uint32_t a[2][4];
            #pragma unroll
            for (int mt = 0; mt < 2; mt++) {
                int r = wm * 32 + mt * 16 + (lane >> 2);
                int c = kk * 8 + (lane & 3);
                a[mt][0] = f2tf32(As[r * 36 + c]);
                a[mt][1] = f2tf32(As[(r + 8) * 36 + c]);
                a[mt][2] = f2tf32(As[r * 36 + c + 4]);
                a[mt][3] = f2tf32(As[(r + 8) * 36 + c + 4]);
            }
            #pragma unroll
            for (int nt = 0; nt < 4; nt++) {
                int n = wn * 32 + nt * 8 + (lane >> 2);
                int k = kk * 8 + (lane & 3);
                uint32_t bg0 = f2tf32(Bg[k * 72 + n]);
                uint32_t bg1 = f2tf32(Bg[(k + 4) * 72 + n]);
                uint32_t bu0 = f2tf32(Bu[k * 72 + n]);
                uint32_t bu1 = f2tf32(Bu[(k + 4) * 72 + n]);
                #pragma unroll
                for (int mt = 0; mt < 2; mt++) {
                    mma8(accg[mt][nt], a[mt], bg0, bg1);
                    mma8(accu[mt][nt], a[mt], bu0, bu1);
                }
            }
        }
    };

    const int NK = Hd / 32;  // 64
    issue(0, 0);
    for (int kt = 0; kt < NK; kt++) {
        if (kt + 1 < NK) {
            issue((kt + 1) & 1, kt + 1);
            asm volatile("cp.async.wait_group 1;\n");
        } else {
            asm volatile("cp.async.wait_group 0;\n");
        }
        __syncthreads();
        compute(kt & 1);
        __syncthreads();
    }

    #pragma unroll
    for (int mt = 0; mt < 2; mt++)
    #pragma unroll
    for (int nt = 0; nt < 4; nt++)
    #pragma unroll
    for (int i = 0; i < 4; i++) {
        int rl = wm * 32 + mt * 16 + (lane >> 2) + (i >> 1) * 8;
        int r = r0 + rl;
        if (r < C) {
            int col = n0 + wn * 32 + nt * 8 + 2 * (lane & 3) + (i & 1);
            float gv = accg[mt][nt][i], uv = accu[mt][nt][i];
            float av = gv / (1.0f + expf(-gv)) * uv;
            ACT[(size_t)(base + r) * N + col] = av;
        }
    }
}

// ---------------- down-proj GEMM (tf32 mma) ----------------
// Tile: 128(M) x 128(N) x 32(K). 256 threads, warps 4x2 (warp = 32x64).
// Stage layout (floats): A[128][36] @0 (4608), B[32][136] @4608 (4352). STAGE = 8960.
template <bool ROUTED>
__global__ void __launch_bounds__(256) down_kernel(const float* __restrict__ Wd,
                                                   float* __restrict__ out,
                                                   int K) {
    extern __shared__ float sm[];
    __shared__ int tok_s[128];
    __shared__ float w_s[128];
    const int tid = threadIdx.x;
    const int lane = tid & 31, wid = tid >> 5;
    const int wm = wid & 3, wn = wid >> 2;
    const int e = blockIdx.z;
    const int n0 = blockIdx.x * 128;
    const int r0 = blockIdx.y * 128;

    int C, base;
    if (ROUTED) { C = g_counts[e]; base = g_offs[e]; }
    else        { C = Td;          base = 0; }
    if (r0 >= C) return;

    const float* A   = ROUTED ? g_act : g_sact;
    const float* WdE = Wd + (size_t)e * K * Hd;

    if (tid < 128) {
        int r = r0 + tid;
        bool v = (r < C);
        tok_s[tid] = v ? (ROUTED ? g_slot_token[base + r] : r) : -1;
        w_s[tid]   = (v && ROUTED) ? g_slot_w[base + r] : 0.f;
    }
    __syncthreads();

    auto issue = [&](int st, int kt) {
        float* As = sm + st * 8960;
        float* Bs = As + 4608;
        int k0 = kt * 32;
        #pragma unroll
        for (int i = 0; i < 4; i++) {
            int idx = tid + i * 256;
            int row = idx >> 3, kc = (idx & 7) * 4;
            bool pred = (r0 + row) < C;
            const float* src = A + (size_t)(base + (pred ? (r0 + row) : 0)) * K + k0 + kc;
            cp16(&As[row * 36 + kc], src, pred);
        }
        #pragma unroll
        for (int i = 0; i < 4; i++) {
            int idx = tid + i * 256;
            int row = idx >> 5, nc = (idx & 31) * 4;
            cp16(&Bs[row * 136 + nc], WdE + (size_t)(k0 + row) * Hd + n0 + nc, true);
        }
        asm volatile("cp.async.commit_group;\n");
    };

    float acc[2][8][4] = {};

    auto compute = [&](int st) {
        const float* As = sm + st * 8960;
        const float* Bs = As + 4608;
        #pragma unroll
        for (int kk = 0; kk < 4; kk++) {
            uint32_t a[2][4];
            #pragma unroll
            for (int mt = 0; mt < 2; mt++) {
                int r = wm * 32 + mt * 16 + (lane >> 2);
                int c = kk * 8 + (lane & 3);
                a[mt][0] = f2tf32(As[r * 36 + c]);
                a[mt][1] = f2tf32(As[(r + 8) * 36 + c]);
                a[mt][2] = f2tf32(As[r * 36 + c + 4]);
                a[mt][3] = f2tf32(As[(r + 8) * 36 + c + 4]);
            }
            #pragma unroll
            for (int nt = 0; nt < 8; nt++) {
                int n = wn * 64 + nt * 8 + (lane >> 2);
                int k = kk * 8 + (lane & 3);
                uint32_t b0 = f2tf32(Bs[k * 136 + n]);
                uint32_t b1 = f2tf32(Bs[(k + 4) * 136 + n]);
                #pragma unroll
                for (int mt = 0; mt < 2; mt++) mma8(acc[mt][nt], a[mt], b0, b1);
            }
        }
    };

    const int NK = K / 32;  // 44 or 88
    issue(0, 0);
    for (int kt = 0; kt < NK; kt++) {
        if (kt + 1 < NK) {
            issue((kt + 1) & 1, kt + 1);
            asm volatile("cp.async.wait_group 1;\n");
        } else {
            asm volatile("cp.async.wait_group 0;\n");
        }
        __syncthreads();
        compute(kt & 1);
        __syncthreads();
    }

    #pragma unroll
    for (int mt = 0; mt < 2; mt++)
    #pragma unroll
    for (int nt = 0; nt < 8; nt++)
    #pragma unroll
    for (int i = 0; i < 4; i++) {
        int rl = wm * 32 + mt * 16 + (lane >> 2) + (i >> 1) * 8;
        int col = n0 + wn * 64 + nt * 8 + 2 * (lane & 3) + (i & 1);
        if (ROUTED) {
            if (r0 + rl < C) {
                int t = tok_s[rl];
                atomicAdd(out + (size_t)t * Hd + col, w_s[rl] * acc[mt][nt][i]);
            }
        } else {
            out[(size_t)(r0 + rl) * Hd + col] = acc[mt][nt][i];
        }
    }
}

// ---------------- launcher ----------------
extern "C" void kernel_launch(void* const* d_in, const int* in_sizes, int n_in,
                              void* d_out, int out_size) {
    (void)in_sizes; (void)n_in; (void)out_size;
    const float* x   = (const float*)d_in[0];
    const float* gw  = (const float*)d_in[1];
    const float* wg  = (const float*)d_in[2];
    const float* wu  = (const float*)d_in[3];
    const float* wd  = (const float*)d_in[4];
    const float* wsg = (const float*)d_in[5];
    const float* wsu = (const float*)d_in[6];
    const float* wsd = (const float*)d_in[7];
    float* out = (float*)d_out;

    cudaFuncSetAttribute(gateup_kernel<true>,  cudaFuncAttributeMaxDynamicSharedMemorySize, 73728);
    cudaFuncSetAttribute(gateup_kernel<false>, cudaFuncAttributeMaxDynamicSharedMemorySize, 73728);
    cudaFuncSetAttribute(down_kernel<true>,    cudaFuncAttributeMaxDynamicSharedMemorySize, 71680);
    cudaFuncSetAttribute(down_kernel<false>,   cudaFuncAttributeMaxDynamicSharedMemorySize, 71680);

    zero_kernel<<<1, 32>>>();
    router_kernel<<<512, 128>>>(x, gw);
    scan_kernel<<<1, 32>>>();
    dispatch_kernel<<<8, 256>>>();

    // routed gate/up: N tiles = 1408/64 = 22, up to 1024 rows/expert (8 tiles), 16 experts
    gateup_kernel<true><<<dim3(22, 8, 16), 256, 73728>>>(x, wg, wu, Id);
    // shared gate/up: N tiles = 2816/64 = 44, 2048 rows (16 tiles)
    gateup_kernel<false><<<dim3(44, 16, 1), 256, 73728>>>(x, wsg, wsu, ISd);
    // shared down first (plain store covers every output element)
    down_kernel<false><<<dim3(16, 16, 1), 256, 71680>>>(wsd, out, ISd);
    // routed down scatters on top via atomicAdd
    down_kernel<true><<<dim3(16, 8, 16), 256, 71680>>>(wd, out, Id);
}